// round 8
// baseline (speedup 1.0000x reference)
#include <cuda_runtime.h>

// ConvexSampler: out = concat(flatten(z), flatten(convex_rows), labels_f32, data_type_f32)
//   z:         (B, D) float32  d_in[0]
//   label_ids: (B,)   int32    d_in[1]
//   data_type: (B,)   float32  d_in[2]
//   pair_idx:  (NC,2) int32    d_in[3]
//   s:         (NC,)  float32  d_in[4]
//   oos_label_id: scalar int   d_in[5] (if present)
//
// Single-wave grid (1184 blocks = 148 SMs x 8 @ 256 thr). Copy blocks run a
// branch-free unroll-8 float4 copy (MLP=8 keeps the read queue full through
// HBM read/write turnarounds). Normal (write-back) stores — evict-first
// regressed steady-state replay. Extras blocks handle convex rows + tails.

#define EX_BLOCKS 16
#define COPY_BLOCKS 1168

__global__ void __launch_bounds__(256, 8)
convex_sampler_fused(const float* __restrict__ z,
                     const int* __restrict__ label_ids,
                     const float* __restrict__ data_type,
                     const int* __restrict__ pair_idx,
                     const float* __restrict__ s,
                     const int* __restrict__ oos_ptr,
                     float* __restrict__ out,
                     int B, int D, int NC)
{
    const long long D4  = D / 4;
    const long long BD4 = (long long)B * D4;      // float4 count of z copy

    const float4* __restrict__ z4  = (const float4*)z;
    float4* __restrict__ out4 = (float4*)out;

    if (blockIdx.x >= EX_BLOCKS) {
        // ---- Region A: bulk copy, branch-free, 8 loads in flight ----
        const long long tcount = (long long)(gridDim.x - EX_BLOCKS) * blockDim.x;
        long long i = (long long)(blockIdx.x - EX_BLOCKS) * blockDim.x + threadIdx.x;

        for (; i + 7 * tcount < BD4; i += 8 * tcount) {
            float4 v0 = z4[i];
            float4 v1 = z4[i + tcount];
            float4 v2 = z4[i + 2 * tcount];
            float4 v3 = z4[i + 3 * tcount];
            float4 v4 = z4[i + 4 * tcount];
            float4 v5 = z4[i + 5 * tcount];
            float4 v6 = z4[i + 6 * tcount];
            float4 v7 = z4[i + 7 * tcount];
            out4[i]              = v0;
            out4[i + tcount]     = v1;
            out4[i + 2 * tcount] = v2;
            out4[i + 3 * tcount] = v3;
            out4[i + 4 * tcount] = v4;
            out4[i + 5 * tcount] = v5;
            out4[i + 6 * tcount] = v6;
            out4[i + 7 * tcount] = v7;
        }
        for (; i < BD4; i += tcount)
            out4[i] = z4[i];
    } else {
        // ---- Extras: convex rows + labels + data_type (tiny; concurrent) ----
        const long long CV4 = (long long)NC * D4;
        const long long NT  = (long long)B + NC;
        const long long scalarBase = (BD4 + CV4) * 4;
        const long long total = CV4 + 2 * NT;

        float oos = 150.0f;
        if (oos_ptr) oos = (float)(*oos_ptr);

        const long long stride = (long long)EX_BLOCKS * blockDim.x;
        for (long long i = (long long)blockIdx.x * blockDim.x + threadIdx.x;
             i < total; i += stride) {
            if (i < CV4) {
                int row  = (int)(i / D4);
                int col4 = (int)(i - (long long)row * D4);
                long long a = (long long)pair_idx[2 * row];
                long long b = (long long)pair_idx[2 * row + 1];
                float sv = s[row];
                float tv = 1.0f - sv;
                float4 za = z4[a * D4 + col4];
                float4 zb = z4[b * D4 + col4];
                float4 r;
                r.x = sv * za.x + tv * zb.x;
                r.y = sv * za.y + tv * zb.y;
                r.z = sv * za.z + tv * zb.z;
                r.w = sv * za.w + tv * zb.w;
                out4[BD4 + i] = r;
            } else if (i < CV4 + NT) {
                long long k = i - CV4;
                float v = (k < B) ? (float)label_ids[k] : oos;
                out[scalarBase + k] = v;
            } else {
                long long k = i - CV4 - NT;
                float v = (k < B) ? data_type[k] : 1.0f;
                out[scalarBase + NT + k] = v;
            }
        }
    }
}

extern "C" void kernel_launch(void* const* d_in, const int* in_sizes, int n_in,
                              void* d_out, int out_size)
{
    const float* z         = (const float*)d_in[0];
    const int*   label_ids = (const int*)d_in[1];
    const float* data_type = (const float*)d_in[2];
    const int*   pair_idx  = (const int*)d_in[3];
    const float* s         = (const float*)d_in[4];
    const int*   oos_ptr   = (n_in >= 6) ? (const int*)d_in[5] : nullptr;

    int B  = in_sizes[1];
    int D  = in_sizes[0] / B;
    int NC = in_sizes[4];

    (void)out_size;

    const int threads = 256;
    const int blocks  = COPY_BLOCKS + EX_BLOCKS;   // 1184 = one full wave
    convex_sampler_fused<<<blocks, threads>>>(z, label_ids, data_type, pair_idx, s,
                                              oos_ptr, (float*)d_out, B, D, NC);
}

// round 9
// speedup vs baseline: 1.0801x; 1.0801x over previous
#include <cuda_runtime.h>

// ConvexSampler: out = concat(flatten(z), flatten(convex_rows), labels_f32, data_type_f32)
//   z:         (B, D) float32  d_in[0]
//   label_ids: (B,)   int32    d_in[1]
//   data_type: (B,)   float32  d_in[2]
//   pair_idx:  (NC,2) int32    d_in[3]
//   s:         (NC,)  float32  d_in[4]
//   oos_label_id: scalar int   d_in[5] (if present)
//
// Grid = exactly two full waves (2 x 1184 = 2368 blocks @ 256 thr, 8 blocks/SM).
// Copy blocks: branch-free unroll-4 float4 copy (MLP=4). Extras blocks handle
// convex rows + label/data_type tails concurrently. Plain write-back stores.

#define EX_BLOCKS 16
#define TOTAL_BLOCKS 2368

__global__ void __launch_bounds__(256, 8)
convex_sampler_fused(const float* __restrict__ z,
                     const int* __restrict__ label_ids,
                     const float* __restrict__ data_type,
                     const int* __restrict__ pair_idx,
                     const float* __restrict__ s,
                     const int* __restrict__ oos_ptr,
                     float* __restrict__ out,
                     int B, int D, int NC)
{
    const long long D4  = D / 4;
    const long long BD4 = (long long)B * D4;      // float4 count of z copy

    const float4* __restrict__ z4  = (const float4*)z;
    float4* __restrict__ out4 = (float4*)out;

    if (blockIdx.x >= EX_BLOCKS) {
        // ---- Region A: bulk copy, branch-free, 4 independent loads in flight ----
        const long long tcount = (long long)(gridDim.x - EX_BLOCKS) * blockDim.x;
        long long i = (long long)(blockIdx.x - EX_BLOCKS) * blockDim.x + threadIdx.x;

        for (; i + 3 * tcount < BD4; i += 4 * tcount) {
            float4 a = z4[i];
            float4 b = z4[i + tcount];
            float4 c = z4[i + 2 * tcount];
            float4 d = z4[i + 3 * tcount];
            out4[i]              = a;
            out4[i + tcount]     = b;
            out4[i + 2 * tcount] = c;
            out4[i + 3 * tcount] = d;
        }
        for (; i < BD4; i += tcount)
            out4[i] = z4[i];
    } else {
        // ---- Extras: convex rows + labels + data_type (tiny; concurrent) ----
        const long long CV4 = (long long)NC * D4;
        const long long NT  = (long long)B + NC;
        const long long scalarBase = (BD4 + CV4) * 4;
        const long long total = CV4 + 2 * NT;

        float oos = 150.0f;
        if (oos_ptr) oos = (float)(*oos_ptr);

        const long long stride = (long long)EX_BLOCKS * blockDim.x;
        for (long long i = (long long)blockIdx.x * blockDim.x + threadIdx.x;
             i < total; i += stride) {
            if (i < CV4) {
                int row  = (int)(i / D4);
                int col4 = (int)(i - (long long)row * D4);
                long long a = (long long)pair_idx[2 * row];
                long long b = (long long)pair_idx[2 * row + 1];
                float sv = s[row];
                float tv = 1.0f - sv;
                float4 za = z4[a * D4 + col4];
                float4 zb = z4[b * D4 + col4];
                float4 r;
                r.x = sv * za.x + tv * zb.x;
                r.y = sv * za.y + tv * zb.y;
                r.z = sv * za.z + tv * zb.z;
                r.w = sv * za.w + tv * zb.w;
                out4[BD4 + i] = r;
            } else if (i < CV4 + NT) {
                long long k = i - CV4;
                float v = (k < B) ? (float)label_ids[k] : oos;
                out[scalarBase + k] = v;
            } else {
                long long k = i - CV4 - NT;
                float v = (k < B) ? data_type[k] : 1.0f;
                out[scalarBase + NT + k] = v;
            }
        }
    }
}

extern "C" void kernel_launch(void* const* d_in, const int* in_sizes, int n_in,
                              void* d_out, int out_size)
{
    const float* z         = (const float*)d_in[0];
    const int*   label_ids = (const int*)d_in[1];
    const float* data_type = (const float*)d_in[2];
    const int*   pair_idx  = (const int*)d_in[3];
    const float* s         = (const float*)d_in[4];
    const int*   oos_ptr   = (n_in >= 6) ? (const int*)d_in[5] : nullptr;

    int B  = in_sizes[1];
    int D  = in_sizes[0] / B;
    int NC = in_sizes[4];

    (void)out_size;

    const int threads = 256;
    convex_sampler_fused<<<TOTAL_BLOCKS, threads>>>(z, label_ids, data_type, pair_idx, s,
                                                    oos_ptr, (float*)d_out, B, D, NC);
}

// round 10
// speedup vs baseline: 1.0885x; 1.0078x over previous
#include <cuda_runtime.h>

// ConvexSampler: out = concat(flatten(z), flatten(convex_rows), labels_f32, data_type_f32)
//   z:         (B, D) float32  d_in[0]
//   label_ids: (B,)   int32    d_in[1]
//   data_type: (B,)   float32  d_in[2]
//   pair_idx:  (NC,2) int32    d_in[3]
//   s:         (NC,)  float32  d_in[4]
//   oos_label_id: scalar int   d_in[5] (if present)
//
// Grid = exactly four full waves (4 x 1184 = 4736 blocks @ 256 thr, 8/SM).
// Copy blocks: branch-free unroll-4 float4 copy (MLP=4). Extras blocks handle
// convex rows + label/data_type tails concurrently. Plain write-back stores.

#define EX_BLOCKS 16
#define TOTAL_BLOCKS 4736

__global__ void __launch_bounds__(256, 8)
convex_sampler_fused(const float* __restrict__ z,
                     const int* __restrict__ label_ids,
                     const float* __restrict__ data_type,
                     const int* __restrict__ pair_idx,
                     const float* __restrict__ s,
                     const int* __restrict__ oos_ptr,
                     float* __restrict__ out,
                     int B, int D, int NC)
{
    const long long D4  = D / 4;
    const long long BD4 = (long long)B * D4;      // float4 count of z copy

    const float4* __restrict__ z4  = (const float4*)z;
    float4* __restrict__ out4 = (float4*)out;

    if (blockIdx.x >= EX_BLOCKS) {
        // ---- Region A: bulk copy, branch-free, 4 independent loads in flight ----
        const long long tcount = (long long)(gridDim.x - EX_BLOCKS) * blockDim.x;
        long long i = (long long)(blockIdx.x - EX_BLOCKS) * blockDim.x + threadIdx.x;

        for (; i + 3 * tcount < BD4; i += 4 * tcount) {
            float4 a = z4[i];
            float4 b = z4[i + tcount];
            float4 c = z4[i + 2 * tcount];
            float4 d = z4[i + 3 * tcount];
            out4[i]              = a;
            out4[i + tcount]     = b;
            out4[i + 2 * tcount] = c;
            out4[i + 3 * tcount] = d;
        }
        for (; i < BD4; i += tcount)
            out4[i] = z4[i];
    } else {
        // ---- Extras: convex rows + labels + data_type (tiny; concurrent) ----
        const long long CV4 = (long long)NC * D4;
        const long long NT  = (long long)B + NC;
        const long long scalarBase = (BD4 + CV4) * 4;
        const long long total = CV4 + 2 * NT;

        float oos = 150.0f;
        if (oos_ptr) oos = (float)(*oos_ptr);

        const long long stride = (long long)EX_BLOCKS * blockDim.x;
        for (long long i = (long long)blockIdx.x * blockDim.x + threadIdx.x;
             i < total; i += stride) {
            if (i < CV4) {
                int row  = (int)(i / D4);
                int col4 = (int)(i - (long long)row * D4);
                long long a = (long long)pair_idx[2 * row];
                long long b = (long long)pair_idx[2 * row + 1];
                float sv = s[row];
                float tv = 1.0f - sv;
                float4 za = z4[a * D4 + col4];
                float4 zb = z4[b * D4 + col4];
                float4 r;
                r.x = sv * za.x + tv * zb.x;
                r.y = sv * za.y + tv * zb.y;
                r.z = sv * za.z + tv * zb.z;
                r.w = sv * za.w + tv * zb.w;
                out4[BD4 + i] = r;
            } else if (i < CV4 + NT) {
                long long k = i - CV4;
                float v = (k < B) ? (float)label_ids[k] : oos;
                out[scalarBase + k] = v;
            } else {
                long long k = i - CV4 - NT;
                float v = (k < B) ? data_type[k] : 1.0f;
                out[scalarBase + NT + k] = v;
            }
        }
    }
}

extern "C" void kernel_launch(void* const* d_in, const int* in_sizes, int n_in,
                              void* d_out, int out_size)
{
    const float* z         = (const float*)d_in[0];
    const int*   label_ids = (const int*)d_in[1];
    const float* data_type = (const float*)d_in[2];
    const int*   pair_idx  = (const int*)d_in[3];
    const float* s         = (const float*)d_in[4];
    const int*   oos_ptr   = (n_in >= 6) ? (const int*)d_in[5] : nullptr;

    int B  = in_sizes[1];
    int D  = in_sizes[0] / B;
    int NC = in_sizes[4];

    (void)out_size;

    const int threads = 256;
    convex_sampler_fused<<<TOTAL_BLOCKS, threads>>>(z, label_ids, data_type, pair_idx, s,
                                                    oos_ptr, (float*)d_out, B, D, NC);
}